// round 1
// baseline (speedup 1.0000x reference)
#include <cuda_runtime.h>

#define BATCH 32
#define C_IN 128
#define C_OUT 256
#define HGT 56
#define WID 56
#define HW 3136
#define BN_EPS 1e-5f
#define DW_THRESH 4.0f
#define PW_THRESH 0.001f

// Scratch (device globals; no allocation allowed)
__device__ float g_y[BATCH * C_IN * HW];        // post-dw activations (after cut1)
__device__ float g_w2t[C_IN * C_OUT];           // transposed, BN2-scaled pointwise weight [ci][co]
__device__ float g_bias2[C_OUT];                // folded pw bias + BN2 shift
__device__ unsigned int g_max[BATCH * C_OUT];   // per (b,co) map max (float bits, values >= 0)

// ---------------------------------------------------------------------------
// K0: fold BN2 into pointwise weights (transpose to [ci][co]) + bias; zero g_max
// ---------------------------------------------------------------------------
__global__ void prep_kernel(const float* __restrict__ pw_w, const float* __restrict__ pw_b,
                            const float* __restrict__ g2, const float* __restrict__ b2,
                            const float* __restrict__ m2, const float* __restrict__ v2)
{
    int t = blockIdx.x * blockDim.x + threadIdx.x;   // 128 blocks * 256 = 32768
    if (t < C_IN * C_OUT) {
        int ci = t / C_OUT;
        int co = t % C_OUT;
        float s2 = g2[co] * rsqrtf(v2[co] + BN_EPS);
        g_w2t[t] = pw_w[co * C_IN + ci] * s2;
    }
    if (t < C_OUT) {
        float s2 = g2[t] * rsqrtf(v2[t] + BN_EPS);
        g_bias2[t] = pw_b[t] * s2 + b2[t] - m2[t] * s2;
    }
    if (t < BATCH * C_OUT) g_max[t] = 0u;
}

// ---------------------------------------------------------------------------
// K1: depthwise 3x3 + bias + BN1 + ReLU + cut(4.0), one block per (b,c) map
// ---------------------------------------------------------------------------
__global__ __launch_bounds__(256) void dw_kernel(
    const float* __restrict__ x,
    const float* __restrict__ dw_w, const float* __restrict__ dw_b,
    const float* __restrict__ g1, const float* __restrict__ b1,
    const float* __restrict__ m1, const float* __restrict__ v1)
{
    __shared__ float xs[HW];
    __shared__ float red[256];

    const int bc = blockIdx.x;            // b*C_IN + c
    const int c  = bc & (C_IN - 1);
    const int t  = threadIdx.x;
    const float* xp = x + (size_t)bc * HW;

    #pragma unroll
    for (int k = 0; k < 13; k++) {
        int p = t + k * 256;
        if (p < HW) xs[p] = xp[p];
    }

    // Fold BN1 scale into weights/bias
    float s1   = g1[c] * rsqrtf(v1[c] + BN_EPS);
    float bias = dw_b[c] * s1 + b1[c] - m1[c] * s1;
    float w00 = dw_w[c*9+0]*s1, w01 = dw_w[c*9+1]*s1, w02 = dw_w[c*9+2]*s1;
    float w10 = dw_w[c*9+3]*s1, w11 = dw_w[c*9+4]*s1, w12 = dw_w[c*9+5]*s1;
    float w20 = dw_w[c*9+6]*s1, w21 = dw_w[c*9+7]*s1, w22 = dw_w[c*9+8]*s1;

    __syncthreads();

    float vals[13];
    float mx = 0.f;
    #pragma unroll
    for (int k = 0; k < 13; k++) {
        int p = t + k * 256;
        if (p < HW) {
            int i = p / WID, j = p - i * WID;
            bool up = (i > 0), dn = (i < HGT - 1), lf = (j > 0), rt = (j < WID - 1);
            float acc = xs[p] * w11;
            if (up) {
                acc += xs[p - WID] * w01;
                if (lf) acc += xs[p - WID - 1] * w00;
                if (rt) acc += xs[p - WID + 1] * w02;
            }
            if (lf) acc += xs[p - 1] * w10;
            if (rt) acc += xs[p + 1] * w12;
            if (dn) {
                acc += xs[p + WID] * w21;
                if (lf) acc += xs[p + WID - 1] * w20;
                if (rt) acc += xs[p + WID + 1] * w22;
            }
            float v = fmaxf(acc + bias, 0.f);
            vals[k] = v;
            mx = fmaxf(mx, v);
        } else {
            vals[k] = 0.f;
        }
    }

    red[t] = mx;
    __syncthreads();
    #pragma unroll
    for (int s = 128; s > 0; s >>= 1) {
        if (t < s) red[t] = fmaxf(red[t], red[t + s]);
        __syncthreads();
    }
    float keep = (red[0] >= DW_THRESH) ? 1.f : 0.f;

    float* yp = g_y + (size_t)bc * HW;
    #pragma unroll
    for (int k = 0; k < 13; k++) {
        int p = t + k * 256;
        if (p < HW) yp[p] = vals[k] * keep;
    }
}

// ---------------------------------------------------------------------------
// K2: pointwise 1x1 as SGEMM (per batch: [3136 x 128] @ [128 x 256])
//     + bias + BN2 (folded) + ReLU, track per-(b,co) max via atomics
//     Tiles: 128 (pixels) x 128 (couts), K-chunk 16, 256 threads, 8x8 per thread
// ---------------------------------------------------------------------------
#define MT 128
#define NT 128
#define KT 16

__global__ __launch_bounds__(256) void pw_kernel(float* __restrict__ out)
{
    __shared__ float As[KT][MT];
    __shared__ float Bs[KT][NT];
    __shared__ unsigned int smax[NT];

    const int b  = blockIdx.z;
    const int m0 = blockIdx.x * MT;     // pixel tile base (0..3072)
    const int n0 = blockIdx.y * NT;     // cout tile base (0 or 128)
    const int t  = threadIdx.x;
    const int tx = t & 15;              // 0..15 (m direction)
    const int ty = t >> 4;              // 0..15 (n direction)

    const float* A = g_y + (size_t)b * C_IN * HW;   // [ci][m], row stride HW

    if (t < NT) smax[t] = 0u;

    float acc[8][8];
    #pragma unroll
    for (int i = 0; i < 8; i++)
        #pragma unroll
        for (int j = 0; j < 8; j++) acc[i][j] = 0.f;

    const int lrow = t >> 5;            // 0..7
    const int lcol = (t & 31) * 4;      // 0..124

    for (int k0 = 0; k0 < C_IN; k0 += KT) {
        __syncthreads();
        // Load A tile: KT x MT
        #pragma unroll
        for (int r = 0; r < 2; r++) {
            int row = r * 8 + lrow;
            int m = m0 + lcol;
            float4 v = make_float4(0.f, 0.f, 0.f, 0.f);
            if (m < HW)
                v = *(const float4*)(A + (size_t)(k0 + row) * HW + m);
            *(float4*)&As[row][lcol] = v;
        }
        // Load B tile: KT x NT from g_w2t [ci][co]
        #pragma unroll
        for (int r = 0; r < 2; r++) {
            int row = r * 8 + lrow;
            float4 v = *(const float4*)(g_w2t + (size_t)(k0 + row) * C_OUT + n0 + lcol);
            *(float4*)&Bs[row][lcol] = v;
        }
        __syncthreads();

        #pragma unroll
        for (int k = 0; k < KT; k++) {
            float a[8], bb[8];
            #pragma unroll
            for (int i = 0; i < 4; i++) {
                a[i]     = As[k][tx * 4 + i];
                a[4 + i] = As[k][64 + tx * 4 + i];
                bb[i]     = Bs[k][ty * 4 + i];
                bb[4 + i] = Bs[k][64 + ty * 4 + i];
            }
            #pragma unroll
            for (int i = 0; i < 8; i++)
                #pragma unroll
                for (int j = 0; j < 8; j++)
                    acc[i][j] += a[i] * bb[j];
        }
    }
    __syncthreads();

    // Epilogue: bias + relu, column max, store
    float* outb = out + ((size_t)b * C_OUT + n0) * HW;
    const int mA = m0 + tx * 4;         // group 0 pixels
    const int mB = m0 + 64 + tx * 4;    // group 1 pixels
    const bool vA = (mA < HW);
    const bool vB = (mB < HW);

    #pragma unroll
    for (int j = 0; j < 8; j++) {
        int nl = (j < 4) ? (ty * 4 + j) : (64 + ty * 4 + (j - 4));
        float bs = g_bias2[n0 + nl];
        float cmax = 0.f;
        float r0[4], r1[4];
        #pragma unroll
        for (int i = 0; i < 4; i++) {
            r0[i] = fmaxf(acc[i][j] + bs, 0.f);
            r1[i] = fmaxf(acc[4 + i][j] + bs, 0.f);
        }
        if (vA) {
            #pragma unroll
            for (int i = 0; i < 4; i++) cmax = fmaxf(cmax, r0[i]);
            *(float4*)&outb[(size_t)nl * HW + mA] = make_float4(r0[0], r0[1], r0[2], r0[3]);
        }
        if (vB) {
            #pragma unroll
            for (int i = 0; i < 4; i++) cmax = fmaxf(cmax, r1[i]);
            *(float4*)&outb[(size_t)nl * HW + mB] = make_float4(r1[0], r1[1], r1[2], r1[3]);
        }
        atomicMax(&smax[nl], __float_as_uint(cmax));
    }
    __syncthreads();
    if (t < NT)
        atomicMax(&g_max[b * C_OUT + n0 + t], smax[t]);
}

// ---------------------------------------------------------------------------
// K3: second cut — zero maps whose max < 0.001 (most pass -> nearly free)
// ---------------------------------------------------------------------------
__global__ void cut_kernel(float* __restrict__ out)
{
    int bc = blockIdx.x;                  // b*C_OUT + co
    float mx = __uint_as_float(g_max[bc]);
    if (mx >= PW_THRESH) return;
    float* p = out + (size_t)bc * HW;
    for (int i = threadIdx.x; i < HW; i += blockDim.x) p[i] = 0.f;
}

// ---------------------------------------------------------------------------
extern "C" void kernel_launch(void* const* d_in, const int* in_sizes, int n_in,
                              void* d_out, int out_size)
{
    const float* x     = (const float*)d_in[0];
    const float* dw_w  = (const float*)d_in[1];
    const float* dw_b  = (const float*)d_in[2];
    const float* bn1_g = (const float*)d_in[3];
    const float* bn1_b = (const float*)d_in[4];
    const float* bn1_m = (const float*)d_in[5];
    const float* bn1_v = (const float*)d_in[6];
    const float* pw_w  = (const float*)d_in[7];
    const float* pw_b  = (const float*)d_in[8];
    const float* bn2_g = (const float*)d_in[9];
    const float* bn2_b = (const float*)d_in[10];
    const float* bn2_m = (const float*)d_in[11];
    const float* bn2_v = (const float*)d_in[12];
    float* out = (float*)d_out;

    prep_kernel<<<128, 256>>>(pw_w, pw_b, bn2_g, bn2_b, bn2_m, bn2_v);
    dw_kernel<<<BATCH * C_IN, 256>>>(x, dw_w, dw_b, bn1_g, bn1_b, bn1_m, bn1_v);
    pw_kernel<<<dim3((HW + MT - 1) / MT, C_OUT / NT, BATCH), 256>>>(out);
    cut_kernel<<<BATCH * C_OUT, 256>>>(out);
}

// round 3
// speedup vs baseline: 1.7346x; 1.7346x over previous
#include <cuda_runtime.h>
#include <cstdint>

#define BATCH 32
#define C_IN 128
#define C_OUT 256
#define HGT 56
#define WID 56
#define HW 3136
#define BN_EPS 1e-5f
#define DW_THRESH 4.0f
#define PW_THRESH 0.001f

#define NTILES 25               // ceil(3136/128) pixel tiles
#define MC 128                  // co per CTA
#define NC 128                  // pixels per CTA
#define KC 64                   // K chunk
#define AS_STRIDE 68            // floats per A row  (128 rows)
#define BS_STRIDE 132           // floats per B row  (64 rows)
#define AS_FLOATS (MC * AS_STRIDE)       // 8704
#define BS_FLOATS (KC * BS_STRIDE)       // 8448
#define PW_SMEM_BYTES ((AS_FLOATS + BS_FLOATS + 128) * 4)

// ---------------- device scratch ----------------
__device__ float g_y[BATCH * C_IN * HW];        // post-dw activations [b][ci][pix] (tf32-rounded)
__device__ float g_w2[C_OUT * C_IN];            // BN2-folded tf32 weights [co][ci]
__device__ float g_bias2[C_OUT];
__device__ unsigned int g_max[BATCH * C_OUT];

__device__ __forceinline__ float tf32_round(float x) {
    uint32_t r;
    asm("cvt.rna.tf32.f32 %0, %1;" : "=r"(r) : "f"(x));
    return __uint_as_float(r);
}

__device__ __forceinline__ void mma_tf32(float* c, const uint32_t* a, const uint32_t* b) {
    asm volatile(
        "mma.sync.aligned.m16n8k8.row.col.f32.tf32.tf32.f32 "
        "{%0,%1,%2,%3}, {%4,%5,%6,%7}, {%8,%9}, {%0,%1,%2,%3};"
        : "+f"(c[0]), "+f"(c[1]), "+f"(c[2]), "+f"(c[3])
        : "r"(a[0]), "r"(a[1]), "r"(a[2]), "r"(a[3]), "r"(b[0]), "r"(b[1]));
}

// ---------------------------------------------------------------------------
// K0: fold BN2 into pointwise weights (tf32-rounded) + bias; zero g_max
// ---------------------------------------------------------------------------
__global__ void prep_kernel(const float* __restrict__ pw_w, const float* __restrict__ pw_b,
                            const float* __restrict__ g2, const float* __restrict__ b2,
                            const float* __restrict__ m2, const float* __restrict__ v2)
{
    int t = blockIdx.x * blockDim.x + threadIdx.x;   // 128 * 256 = 32768
    if (t < C_OUT * C_IN) {
        int co = t >> 7;
        float s2 = g2[co] * rsqrtf(v2[co] + BN_EPS);
        g_w2[t] = tf32_round(pw_w[t] * s2);
    }
    if (t < C_OUT) {
        float s2 = g2[t] * rsqrtf(v2[t] + BN_EPS);
        g_bias2[t] = pw_b[t] * s2 + b2[t] - m2[t] * s2;
    }
    if (t < BATCH * C_OUT) g_max[t] = 0u;
}

// ---------------------------------------------------------------------------
// K1: depthwise 3x3 + bias + BN1 + ReLU + cut(4.0), one block per (b,c) map
// ---------------------------------------------------------------------------
__global__ __launch_bounds__(256) void dw_kernel(
    const float* __restrict__ x,
    const float* __restrict__ dw_w, const float* __restrict__ dw_b,
    const float* __restrict__ g1, const float* __restrict__ b1,
    const float* __restrict__ m1, const float* __restrict__ v1)
{
    __shared__ float xs[HW];
    __shared__ float red[256];

    const int bc = blockIdx.x;
    const int c  = bc & (C_IN - 1);
    const int t  = threadIdx.x;
    const float* xp = x + (size_t)bc * HW;

    #pragma unroll
    for (int k = 0; k < 13; k++) {
        int p = t + k * 256;
        if (p < HW) xs[p] = xp[p];
    }

    float s1   = g1[c] * rsqrtf(v1[c] + BN_EPS);
    float bias = dw_b[c] * s1 + b1[c] - m1[c] * s1;
    float w00 = dw_w[c*9+0]*s1, w01 = dw_w[c*9+1]*s1, w02 = dw_w[c*9+2]*s1;
    float w10 = dw_w[c*9+3]*s1, w11 = dw_w[c*9+4]*s1, w12 = dw_w[c*9+5]*s1;
    float w20 = dw_w[c*9+6]*s1, w21 = dw_w[c*9+7]*s1, w22 = dw_w[c*9+8]*s1;

    __syncthreads();

    float vals[13];
    float mx = 0.f;
    #pragma unroll
    for (int k = 0; k < 13; k++) {
        int p = t + k * 256;
        if (p < HW) {
            int i = p / WID, j = p - i * WID;
            bool up = (i > 0), dn = (i < HGT - 1), lf = (j > 0), rt = (j < WID - 1);
            float acc = xs[p] * w11;
            if (up) {
                acc += xs[p - WID] * w01;
                if (lf) acc += xs[p - WID - 1] * w00;
                if (rt) acc += xs[p - WID + 1] * w02;
            }
            if (lf) acc += xs[p - 1] * w10;
            if (rt) acc += xs[p + 1] * w12;
            if (dn) {
                acc += xs[p + WID] * w21;
                if (lf) acc += xs[p + WID - 1] * w20;
                if (rt) acc += xs[p + WID + 1] * w22;
            }
            float v = fmaxf(acc + bias, 0.f);
            vals[k] = v;
            mx = fmaxf(mx, v);
        } else {
            vals[k] = 0.f;
        }
    }

    red[t] = mx;
    __syncthreads();
    #pragma unroll
    for (int s = 128; s > 0; s >>= 1) {
        if (t < s) red[t] = fmaxf(red[t], red[t + s]);
        __syncthreads();
    }
    float keep = (red[0] >= DW_THRESH) ? 1.f : 0.f;

    float* yp = g_y + (size_t)bc * HW;
    #pragma unroll
    for (int k = 0; k < 13; k++) {
        int p = t + k * 256;
        if (p < HW) yp[p] = tf32_round(vals[k] * keep);
    }
}

// ---------------------------------------------------------------------------
// K2: pointwise GEMM via mma.sync tf32.
//     M = co (128/CTA), N = pix (128/CTA), K = ci (128, chunks of 64).
//     8 warps, warp tile 32 co x 64 pix. Epilogue: bias+relu+max+store.
// ---------------------------------------------------------------------------
__global__ __launch_bounds__(256) void pw_kernel(float* __restrict__ out)
{
    extern __shared__ float smem[];
    float* As = smem;                       // [128 co][AS_STRIDE]
    float* Bs = smem + AS_FLOATS;           // [64 k][BS_STRIDE]
    unsigned int* smax = (unsigned int*)(smem + AS_FLOATS + BS_FLOATS);  // [128]

    const int co0  = blockIdx.x * MC;       // 0 or 128
    const int pix0 = blockIdx.y * NC;       // 0..3072
    const int b    = blockIdx.z;
    const int t    = threadIdx.x;
    const int w    = t >> 5;
    const int lane = t & 31;
    const int g    = lane >> 2;             // group id 0..7
    const int tg   = lane & 3;              // thread in group 0..3
    const int wm   = w >> 1;                // 0..3  (co)
    const int wn   = w & 1;                 // 0..1  (pix)

    const float* yb = g_y + (size_t)b * C_IN * HW;

    if (t < MC) smax[t] = 0u;

    float c[2][8][4];
    #pragma unroll
    for (int mt = 0; mt < 2; mt++)
        #pragma unroll
        for (int nt = 0; nt < 8; nt++)
            #pragma unroll
            for (int i = 0; i < 4; i++) c[mt][nt][i] = 0.f;

    for (int kc0 = 0; kc0 < C_IN; kc0 += KC) {
        __syncthreads();
        // Load A (weights): 128 co x 64 k, float4
        #pragma unroll
        for (int i = 0; i < 8; i++) {
            int id = i * 256 + t;
            int co = id >> 4;
            int kq = (id & 15) * 4;
            float4 v = *(const float4*)(g_w2 + (size_t)(co0 + co) * C_IN + kc0 + kq);
            *(float4*)(As + co * AS_STRIDE + kq) = v;
        }
        // Load B (activations): 64 k x 128 pix, float4 (zero-pad past HW)
        #pragma unroll
        for (int i = 0; i < 8; i++) {
            int id = i * 256 + t;
            int k  = id >> 5;
            int pq = (id & 31) * 4;
            int pix = pix0 + pq;
            float4 v = make_float4(0.f, 0.f, 0.f, 0.f);
            if (pix < HW)
                v = *(const float4*)(yb + (size_t)(kc0 + k) * HW + pix);
            *(float4*)(Bs + k * BS_STRIDE + pq) = v;
        }
        __syncthreads();

        #pragma unroll
        for (int ks = 0; ks < KC / 8; ks++) {
            uint32_t a[2][4], bf[8][2];
            #pragma unroll
            for (int mt = 0; mt < 2; mt++) {
                int row = wm * 32 + mt * 16 + g;
                int kk  = ks * 8 + tg;
                a[mt][0] = __float_as_uint(As[row * AS_STRIDE + kk]);
                a[mt][1] = __float_as_uint(As[(row + 8) * AS_STRIDE + kk]);
                a[mt][2] = __float_as_uint(As[row * AS_STRIDE + kk + 4]);
                a[mt][3] = __float_as_uint(As[(row + 8) * AS_STRIDE + kk + 4]);
            }
            #pragma unroll
            for (int nt = 0; nt < 8; nt++) {
                int col = wn * 64 + nt * 8 + g;
                int kk  = ks * 8 + tg;
                bf[nt][0] = __float_as_uint(Bs[kk * BS_STRIDE + col]);
                bf[nt][1] = __float_as_uint(Bs[(kk + 4) * BS_STRIDE + col]);
            }
            #pragma unroll
            for (int mt = 0; mt < 2; mt++)
                #pragma unroll
                for (int nt = 0; nt < 8; nt++)
                    mma_tf32(c[mt][nt], a[mt], bf[nt]);
        }
    }

    // Epilogue
    float* outb = out + (size_t)b * C_OUT * HW;
    #pragma unroll
    for (int mt = 0; mt < 2; mt++) {
        #pragma unroll
        for (int half = 0; half < 2; half++) {
            int co_l = wm * 32 + mt * 16 + half * 8 + g;      // 0..127 within tile
            int co   = co0 + co_l;
            float bs = g_bias2[co];
            float mxv = 0.f;
            float* orow = outb + (size_t)co * HW;
            #pragma unroll
            for (int nt = 0; nt < 8; nt++) {
                float v0 = fmaxf(c[mt][nt][half * 2 + 0] + bs, 0.f);
                float v1 = fmaxf(c[mt][nt][half * 2 + 1] + bs, 0.f);
                int pix = pix0 + wn * 64 + nt * 8 + tg * 2;
                if (pix < HW) {
                    mxv = fmaxf(mxv, fmaxf(v0, v1));
                    *(float2*)(orow + pix) = make_float2(v0, v1);
                }
            }
            // reduce max over the 4 lanes of the quad (same co row)
            mxv = fmaxf(mxv, __shfl_xor_sync(0xffffffffu, mxv, 1));
            mxv = fmaxf(mxv, __shfl_xor_sync(0xffffffffu, mxv, 2));
            if (tg == 0) atomicMax(&smax[co_l], __float_as_uint(mxv));
        }
    }
    __syncthreads();
    if (t < MC) atomicMax(&g_max[b * C_OUT + co0 + t], smax[t]);
}

// ---------------------------------------------------------------------------
// K3: second cut — zero maps whose max < 0.001
// ---------------------------------------------------------------------------
__global__ void cut_kernel(float* __restrict__ out)
{
    int bc = blockIdx.x;
    float mx = __uint_as_float(g_max[bc]);
    if (mx >= PW_THRESH) return;
    float4* p = (float4*)(out + (size_t)bc * HW);
    for (int i = threadIdx.x; i < HW / 4; i += blockDim.x)
        p[i] = make_float4(0.f, 0.f, 0.f, 0.f);
}

// ---------------------------------------------------------------------------
extern "C" void kernel_launch(void* const* d_in, const int* in_sizes, int n_in,
                              void* d_out, int out_size)
{
    const float* x     = (const float*)d_in[0];
    const float* dw_w  = (const float*)d_in[1];
    const float* dw_b  = (const float*)d_in[2];
    const float* bn1_g = (const float*)d_in[3];
    const float* bn1_b = (const float*)d_in[4];
    const float* bn1_m = (const float*)d_in[5];
    const float* bn1_v = (const float*)d_in[6];
    const float* pw_w  = (const float*)d_in[7];
    const float* pw_b  = (const float*)d_in[8];
    const float* bn2_g = (const float*)d_in[9];
    const float* bn2_b = (const float*)d_in[10];
    const float* bn2_m = (const float*)d_in[11];
    const float* bn2_v = (const float*)d_in[12];
    float* out = (float*)d_out;

    static bool attrs_set = false;
    if (!attrs_set) {
        cudaFuncSetAttribute(pw_kernel, cudaFuncAttributeMaxDynamicSharedMemorySize, PW_SMEM_BYTES);
        attrs_set = true;
    }

    prep_kernel<<<128, 256>>>(pw_w, pw_b, bn2_g, bn2_b, bn2_m, bn2_v);
    dw_kernel<<<BATCH * C_IN, 256>>>(x, dw_w, dw_b, bn1_g, bn1_b, bn1_m, bn1_v);
    pw_kernel<<<dim3(C_OUT / MC, NTILES, BATCH), 256, PW_SMEM_BYTES>>>(out);
    cut_kernel<<<BATCH * C_OUT, 256>>>(out);
}

// round 4
// speedup vs baseline: 2.3281x; 1.3422x over previous
#include <cuda_runtime.h>
#include <cuda_fp16.h>
#include <cstdint>

#define BATCH 32
#define C_IN 128
#define C_OUT 256
#define HGT 56
#define WID 56
#define HW 3136
#define BN_EPS 1e-5f
#define DW_THRESH 4.0f
#define PW_THRESH 0.001f

#define NTILES 25               // ceil(3136/128) pixel tiles
#define MC 128                  // co per CTA
#define NC 128                  // pixels per CTA
#define SSTR 136                // smem row stride in halfs (128 + 8 pad)
#define AS_HALFS (128 * SSTR)   // 17408
#define BS_HALFS (128 * SSTR)
#define PW_SMEM_BYTES ((AS_HALFS + BS_HALFS) * 2 + 512)

// ---------------- device scratch ----------------
__device__ __half g_y[BATCH * C_IN * HW];       // post-dw activations [b][ci][pix]
__device__ __half g_w2[C_OUT * C_IN];           // BN2-folded weights [co][ci]
__device__ float g_bias2[C_OUT];
__device__ unsigned int g_max[BATCH * C_OUT];

__device__ __forceinline__ void ldsm_x4(uint32_t* r, uint32_t addr) {
    asm volatile("ldmatrix.sync.aligned.m8n8.x4.shared.b16 {%0,%1,%2,%3}, [%4];"
                 : "=r"(r[0]), "=r"(r[1]), "=r"(r[2]), "=r"(r[3]) : "r"(addr));
}
__device__ __forceinline__ void ldsm_x4_t(uint32_t* r, uint32_t addr) {
    asm volatile("ldmatrix.sync.aligned.m8n8.x4.trans.shared.b16 {%0,%1,%2,%3}, [%4];"
                 : "=r"(r[0]), "=r"(r[1]), "=r"(r[2]), "=r"(r[3]) : "r"(addr));
}
__device__ __forceinline__ void mma_f16(float* c, const uint32_t* a, const uint32_t* b) {
    asm volatile(
        "mma.sync.aligned.m16n8k16.row.col.f32.f16.f16.f32 "
        "{%0,%1,%2,%3}, {%4,%5,%6,%7}, {%8,%9}, {%0,%1,%2,%3};"
        : "+f"(c[0]), "+f"(c[1]), "+f"(c[2]), "+f"(c[3])
        : "r"(a[0]), "r"(a[1]), "r"(a[2]), "r"(a[3]), "r"(b[0]), "r"(b[1]));
}

// ---------------------------------------------------------------------------
// K0: fold BN2 into pointwise weights (fp16) + bias; zero g_max
// ---------------------------------------------------------------------------
__global__ void prep_kernel(const float* __restrict__ pw_w, const float* __restrict__ pw_b,
                            const float* __restrict__ g2, const float* __restrict__ b2,
                            const float* __restrict__ m2, const float* __restrict__ v2)
{
    int t = blockIdx.x * blockDim.x + threadIdx.x;   // 128 * 256 = 32768
    if (t < C_OUT * C_IN) {
        int co = t >> 7;
        float s2 = g2[co] * rsqrtf(v2[co] + BN_EPS);
        g_w2[t] = __float2half(pw_w[t] * s2);
    }
    if (t < C_OUT) {
        float s2 = g2[t] * rsqrtf(v2[t] + BN_EPS);
        g_bias2[t] = pw_b[t] * s2 + b2[t] - m2[t] * s2;
    }
    if (t < BATCH * C_OUT) g_max[t] = 0u;
}

// ---------------------------------------------------------------------------
// K1: depthwise 3x3 + bias + BN1 + ReLU + cut(4.0), one block per (b,c) map
// ---------------------------------------------------------------------------
__global__ __launch_bounds__(256) void dw_kernel(
    const float* __restrict__ x,
    const float* __restrict__ dw_w, const float* __restrict__ dw_b,
    const float* __restrict__ g1, const float* __restrict__ b1,
    const float* __restrict__ m1, const float* __restrict__ v1)
{
    __shared__ float xs[HW];
    __shared__ float red[256];

    const int bc = blockIdx.x;
    const int c  = bc & (C_IN - 1);
    const int t  = threadIdx.x;
    const float* xp = x + (size_t)bc * HW;

    #pragma unroll
    for (int k = 0; k < 13; k++) {
        int p = t + k * 256;
        if (p < HW) xs[p] = xp[p];
    }

    float s1   = g1[c] * rsqrtf(v1[c] + BN_EPS);
    float bias = dw_b[c] * s1 + b1[c] - m1[c] * s1;
    float w00 = dw_w[c*9+0]*s1, w01 = dw_w[c*9+1]*s1, w02 = dw_w[c*9+2]*s1;
    float w10 = dw_w[c*9+3]*s1, w11 = dw_w[c*9+4]*s1, w12 = dw_w[c*9+5]*s1;
    float w20 = dw_w[c*9+6]*s1, w21 = dw_w[c*9+7]*s1, w22 = dw_w[c*9+8]*s1;

    __syncthreads();

    float vals[13];
    float mx = 0.f;
    #pragma unroll
    for (int k = 0; k < 13; k++) {
        int p = t + k * 256;
        if (p < HW) {
            int i = p / WID, j = p - i * WID;
            bool up = (i > 0), dn = (i < HGT - 1), lf = (j > 0), rt = (j < WID - 1);
            float acc = xs[p] * w11;
            if (up) {
                acc += xs[p - WID] * w01;
                if (lf) acc += xs[p - WID - 1] * w00;
                if (rt) acc += xs[p - WID + 1] * w02;
            }
            if (lf) acc += xs[p - 1] * w10;
            if (rt) acc += xs[p + 1] * w12;
            if (dn) {
                acc += xs[p + WID] * w21;
                if (lf) acc += xs[p + WID - 1] * w20;
                if (rt) acc += xs[p + WID + 1] * w22;
            }
            float v = fmaxf(acc + bias, 0.f);
            vals[k] = v;
            mx = fmaxf(mx, v);
        } else {
            vals[k] = 0.f;
        }
    }

    red[t] = mx;
    __syncthreads();
    #pragma unroll
    for (int s = 128; s > 0; s >>= 1) {
        if (t < s) red[t] = fmaxf(red[t], red[t + s]);
        __syncthreads();
    }
    float keep = (red[0] >= DW_THRESH) ? 1.f : 0.f;

    __half* yp = g_y + (size_t)bc * HW;
    #pragma unroll
    for (int k = 0; k < 13; k++) {
        int p = t + k * 256;
        if (p < HW) yp[p] = __float2half(vals[k] * keep);
    }
}

// ---------------------------------------------------------------------------
// K2: pointwise GEMM via mma.sync fp16 (f32 accum).
//     M = co (128/CTA), N = pix (128/CTA), K = ci (128, single stage).
//     8 warps, warp tile 32 co x 64 pix. ldmatrix-fed fragments.
// ---------------------------------------------------------------------------
__global__ __launch_bounds__(256) void pw_kernel(float* __restrict__ out)
{
    extern __shared__ __half smem[];
    __half* As = smem;                       // [128 co][SSTR]
    __half* Bs = smem + AS_HALFS;            // [128 k][SSTR]
    unsigned int* smax = (unsigned int*)(smem + AS_HALFS + BS_HALFS);  // [128]

    const int co0  = blockIdx.x * MC;        // 0 or 128
    const int pix0 = blockIdx.y * NC;        // 0..3072
    const int b    = blockIdx.z;
    const int t    = threadIdx.x;
    const int w    = t >> 5;
    const int lane = t & 31;
    const int g    = lane >> 2;
    const int tg   = lane & 3;
    const int wm   = w >> 1;                 // 0..3 (co)
    const int wn   = w & 1;                  // 0..1 (pix)

    const __half* yb = g_y + (size_t)b * C_IN * HW;

    if (t < MC) smax[t] = 0u;

    // ---- fill smem (whole K at once): A = weights, B = activations ----
    // A: 128 rows x 256B from g_w2[co0..co0+127][.]; 2048 uint4 total
    {
        const uint4* src = (const uint4*)(g_w2 + (size_t)co0 * C_IN);
        #pragma unroll
        for (int i = 0; i < 8; i++) {
            int id = i * 256 + t;
            int co = id >> 4;
            int kq = (id & 15);              // 16B chunk: 8 halfs
            uint4 v = src[co * 16 + kq];
            *(uint4*)(As + co * SSTR + kq * 8) = v;
        }
    }
    // B: 128 rows x 256B from yb[k][pix0..pix0+127] (zero-pad past HW)
    {
        #pragma unroll
        for (int i = 0; i < 8; i++) {
            int id = i * 256 + t;
            int k  = id >> 4;
            int pq = (id & 15);
            int pix = pix0 + pq * 8;
            uint4 v = make_uint4(0u, 0u, 0u, 0u);
            if (pix < HW)
                v = *(const uint4*)(yb + (size_t)k * HW + pix);
            *(uint4*)(Bs + k * SSTR + pq * 8) = v;
        }
    }
    __syncthreads();

    // ---- ldmatrix base addresses ----
    uint32_t as_addr = (uint32_t)__cvta_generic_to_shared(As);
    uint32_t bs_addr = (uint32_t)__cvta_generic_to_shared(Bs);
    // A: lanes 0-15 -> rows (lane&15), lanes 16-31 -> same rows, k+8
    uint32_t a_base = as_addr + (((wm * 32 + (lane & 15)) * SSTR + (lane >> 4) * 8) << 1);
    // B(trans): lanes 0-15 -> k rows (lane&15), lanes 16-31 -> cols +8
    uint32_t b_base = bs_addr + ((((lane & 15)) * SSTR + wn * 64 + (lane >> 4) * 8) << 1);

    float c[2][8][4];
    #pragma unroll
    for (int mt = 0; mt < 2; mt++)
        #pragma unroll
        for (int nt = 0; nt < 8; nt++)
            #pragma unroll
            for (int i = 0; i < 4; i++) c[mt][nt][i] = 0.f;

    #pragma unroll
    for (int ks = 0; ks < 8; ks++) {
        uint32_t a[2][4], bb[4][4];
        #pragma unroll
        for (int mt = 0; mt < 2; mt++)
            ldsm_x4(a[mt], a_base + mt * (16 * SSTR * 2) + ks * 32);
        #pragma unroll
        for (int ntp = 0; ntp < 4; ntp++)
            ldsm_x4_t(bb[ntp], b_base + ntp * 32 + ks * (16 * SSTR * 2));
        #pragma unroll
        for (int mt = 0; mt < 2; mt++) {
            #pragma unroll
            for (int ntp = 0; ntp < 4; ntp++) {
                mma_f16(c[mt][ntp * 2 + 0], a[mt], &bb[ntp][0]);
                mma_f16(c[mt][ntp * 2 + 1], a[mt], &bb[ntp][2]);
            }
        }
    }

    // ---- epilogue: bias + relu + per-co max + store ----
    float* outb = out + (size_t)b * C_OUT * HW;
    #pragma unroll
    for (int mt = 0; mt < 2; mt++) {
        #pragma unroll
        for (int half = 0; half < 2; half++) {
            int co_l = wm * 32 + mt * 16 + half * 8 + g;
            int co   = co0 + co_l;
            float bs = g_bias2[co];
            float mxv = 0.f;
            float* orow = outb + (size_t)co * HW;
            #pragma unroll
            for (int nt = 0; nt < 8; nt++) {
                float v0 = fmaxf(c[mt][nt][half * 2 + 0] + bs, 0.f);
                float v1 = fmaxf(c[mt][nt][half * 2 + 1] + bs, 0.f);
                int pix = pix0 + wn * 64 + nt * 8 + tg * 2;
                if (pix < HW) {
                    mxv = fmaxf(mxv, fmaxf(v0, v1));
                    *(float2*)(orow + pix) = make_float2(v0, v1);
                }
            }
            mxv = fmaxf(mxv, __shfl_xor_sync(0xffffffffu, mxv, 1));
            mxv = fmaxf(mxv, __shfl_xor_sync(0xffffffffu, mxv, 2));
            if (tg == 0) atomicMax(&smax[co_l], __float_as_uint(mxv));
        }
    }
    __syncthreads();
    if (t < MC) atomicMax(&g_max[b * C_OUT + co0 + t], smax[t]);
}

// ---------------------------------------------------------------------------
// K3: second cut — zero maps whose max < 0.001
// ---------------------------------------------------------------------------
__global__ void cut_kernel(float* __restrict__ out)
{
    int bc = blockIdx.x;
    float mx = __uint_as_float(g_max[bc]);
    if (mx >= PW_THRESH) return;
    float4* p = (float4*)(out + (size_t)bc * HW);
    for (int i = threadIdx.x; i < HW / 4; i += blockDim.x)
        p[i] = make_float4(0.f, 0.f, 0.f, 0.f);
}

// ---------------------------------------------------------------------------
extern "C" void kernel_launch(void* const* d_in, const int* in_sizes, int n_in,
                              void* d_out, int out_size)
{
    const float* x     = (const float*)d_in[0];
    const float* dw_w  = (const float*)d_in[1];
    const float* dw_b  = (const float*)d_in[2];
    const float* bn1_g = (const float*)d_in[3];
    const float* bn1_b = (const float*)d_in[4];
    const float* bn1_m = (const float*)d_in[5];
    const float* bn1_v = (const float*)d_in[6];
    const float* pw_w  = (const float*)d_in[7];
    const float* pw_b  = (const float*)d_in[8];
    const float* bn2_g = (const float*)d_in[9];
    const float* bn2_b = (const float*)d_in[10];
    const float* bn2_m = (const float*)d_in[11];
    const float* bn2_v = (const float*)d_in[12];
    float* out = (float*)d_out;

    static bool attrs_set = false;
    if (!attrs_set) {
        cudaFuncSetAttribute(pw_kernel, cudaFuncAttributeMaxDynamicSharedMemorySize, PW_SMEM_BYTES);
        attrs_set = true;
    }

    prep_kernel<<<128, 256>>>(pw_w, pw_b, bn2_g, bn2_b, bn2_m, bn2_v);
    dw_kernel<<<BATCH * C_IN, 256>>>(x, dw_w, dw_b, bn1_g, bn1_b, bn1_m, bn1_v);
    pw_kernel<<<dim3(C_OUT / MC, NTILES, BATCH), 256, PW_SMEM_BYTES>>>(out);
    cut_kernel<<<BATCH * C_OUT, 256>>>(out);
}